// round 15
// baseline (speedup 1.0000x reference)
#include <cuda_runtime.h>
#include <math.h>

#define BS 8
#define LQ 300
#define NQ (BS*LQ)        // 2400
#define DIM 256
#define NH 8
#define NL 4
#define NP 4
#define LEN_V 34000
#define NPOINT 128        // NH*NL*NP

__constant__ int c_lvlW[4]     = {160, 80, 40, 20};
__constant__ int c_lvlStart[4] = {0, 25600, 32000, 33600};

// Scratch
__device__ float g_P[NQ * 384];                    // [off(256) | attn(128)]
__device__ float g_agg[(size_t)NH * NQ * DIM];     // [h][q][c]
__device__ float g_wsum[NQ * NH];
__device__ float g_Y[NQ * DIM];

// ---------------------------------------------------------------------------
// R5 GEMM (frozen): tile 32(M) x 64(N), 128 threads, micro 4x4, double-buffer.
// ---------------------------------------------------------------------------
__global__ void gemm_dual_kernel(const float* __restrict__ A, int lda,
                                 const float* __restrict__ W0,
                                 const float* __restrict__ b0, int nyW0,
                                 const float* __restrict__ W1,
                                 const float* __restrict__ b1,
                                 float* __restrict__ C, int ldc, int M)
{
    __shared__ float As[2][16][36];
    __shared__ float Bs[2][16][68];
    const int tid = threadIdx.x;
    const int tx = tid & 7;           // m-quad
    const int ty = tid >> 3;          // n-quad 0..15
    const int row0 = blockIdx.x * 32;
    const int ar = tid >> 2;          // 0..31 (A load row)
    const int akq = (tid & 3) * 4;
    const int br = tid >> 1;          // 0..63 (B load col)
    const int bkq = (tid & 1) * 8;

    const float* W; const float* bias; int col0, colOff;
    if ((int)blockIdx.y < nyW0) {
        W = W0; bias = b0; col0 = blockIdx.y * 64; colOff = 0;
    } else {
        W = W1; bias = b1; col0 = (blockIdx.y - nyW0) * 64; colOff = nyW0 * 64;
    }

    int arow = row0 + ar; if (arow >= M) arow = M - 1;
    const float* aptr = A + (size_t)arow * lda + akq;
    const float* wptr = W + (size_t)(col0 + br) * 256 + bkq;

    float acc[2][4];
    float acc2[2][4];
#pragma unroll
    for (int i = 0; i < 2; ++i)
#pragma unroll
        for (int j = 0; j < 4; ++j) { acc[i][j] = 0.f; acc2[i][j] = 0.f; }

    float4 va  = *(const float4*)(aptr);
    float4 vw0 = *(const float4*)(wptr);
    float4 vw1 = *(const float4*)(wptr + 4);

    int buf = 0;
    for (int kc = 0; kc < 256; kc += 16) {
        As[buf][akq + 0][ar] = va.x;  As[buf][akq + 1][ar] = va.y;
        As[buf][akq + 2][ar] = va.z;  As[buf][akq + 3][ar] = va.w;
        Bs[buf][bkq + 0][br] = vw0.x; Bs[buf][bkq + 1][br] = vw0.y;
        Bs[buf][bkq + 2][br] = vw0.z; Bs[buf][bkq + 3][br] = vw0.w;
        Bs[buf][bkq + 4][br] = vw1.x; Bs[buf][bkq + 5][br] = vw1.y;
        Bs[buf][bkq + 6][br] = vw1.z; Bs[buf][bkq + 7][br] = vw1.w;
        __syncthreads();
        if (kc + 16 < 256) {
            va  = *(const float4*)(aptr + kc + 16);
            vw0 = *(const float4*)(wptr + kc + 16);
            vw1 = *(const float4*)(wptr + kc + 20);
        }
#pragma unroll
        for (int k = 0; k < 16; ++k) {
            float4 a4 = ((const float4*)As[buf][k])[tx];
            float4 b4 = ((const float4*)Bs[buf][k])[ty];
            acc[0][0] += a4.x * b4.x; acc[0][1] += a4.x * b4.y;
            acc[0][2] += a4.x * b4.z; acc[0][3] += a4.x * b4.w;
            acc[1][0] += a4.y * b4.x; acc[1][1] += a4.y * b4.y;
            acc[1][2] += a4.y * b4.z; acc[1][3] += a4.y * b4.w;
            acc2[0][0] += a4.z * b4.x; acc2[0][1] += a4.z * b4.y;
            acc2[0][2] += a4.z * b4.z; acc2[0][3] += a4.z * b4.w;
            acc2[1][0] += a4.w * b4.x; acc2[1][1] += a4.w * b4.y;
            acc2[1][2] += a4.w * b4.z; acc2[1][3] += a4.w * b4.w;
        }
        buf ^= 1;
    }

    const int gc = col0 + ty * 4;
    float4 bv4 = make_float4(bias[gc], bias[gc + 1], bias[gc + 2], bias[gc + 3]);
#pragma unroll
    for (int i = 0; i < 4; ++i) {
        int r = row0 + tx * 4 + i;
        if (r < M) {
            float* a = (i < 2) ? acc[i] : acc2[i - 2];
            float4 o = make_float4(a[0] + bv4.x, a[1] + bv4.y,
                                   a[2] + bv4.z, a[3] + bv4.w);
            *(float4*)(&C[(size_t)r * ldc + colOff + gc]) = o;
        }
    }
}

// ---------------------------------------------------------------------------
// Fused prep + warp-local shuffle dedup + compact + HIGH-MLP gather.
// Count padded to multiple of 16; gather loop issues 16 LDG.128 per batch.
// ---------------------------------------------------------------------------
__global__ void gather_kernel(const float* __restrict__ value,
                              const float* __restrict__ refpts)
{
    __shared__ float  sm_aw[NPOINT];
    __shared__ __align__(16) float2 sC[NH][80];  // compacted (w, idx), padded
    __shared__ int    sCnt[NH];

    const int bq = blockIdx.x;
    const int b = bq / LQ;
    const int tid = threadIdx.x;
    const int h = tid >> 5;           // warp = head
    const int lane = tid & 31;

    if (tid < NPOINT) sm_aw[tid] = g_P[bq * 384 + 256 + tid];
    __syncthreads();

    // ---- softmax over head's 16 logits (width-16 shuffle reduction) ----
    const int pih = lane >> 1;        // point-in-head 0..15 (l = pih>>2)
    float v = sm_aw[h * 16 + (lane & 15)];
    float mx = v;
#pragma unroll
    for (int m = 8; m > 0; m >>= 1)
        mx = fmaxf(mx, __shfl_xor_sync(0xffffffffu, mx, m, 16));
    float e = expf(v - mx);
    float ssum = e;
#pragma unroll
    for (int m = 8; m > 0; m >>= 1)
        ssum += __shfl_xor_sync(0xffffffffu, ssum, m, 16);
    float aw = expf(sm_aw[h * 16 + pih] - mx) / ssum;

    // ---- sampling location for my point; my two taps ----
    const int l = pih >> 2;
    const int Wl = c_lvlW[l];
    const int base = c_lvlStart[l];
    const float fW = (float)Wl;
    float offx = g_P[bq * 384 + (h * 16 + pih) * 2 + 0];
    float offy = g_P[bq * 384 + (h * 16 + pih) * 2 + 1];
    float rx = refpts[(bq * NL + l) * 2 + 0];
    float ry = refpts[(bq * NL + l) * 2 + 1];
    float x = (rx + offx / fW) * fW - 0.5f;
    float y = (ry + offy / fW) * fW - 0.5f;
    const float fx = floorf(x), fy = floorf(y);
    const int x0 = (int)fx, y0 = (int)fy;
    const float wx = x - fx, wy = y - fy;

    const int tb = (lane & 1) * 2;    // taps tb, tb+1
    int   tidx[2]; float twt[2];
    float tsum = 0.f;
#pragma unroll
    for (int k = 0; k < 2; ++k) {
        const int t = tb + k;
        const int xi = x0 + (t & 1), yi = y0 + (t >> 1);
        bool valid = (xi >= 0) && (xi < Wl) && (yi >= 0) && (yi < Wl);
        float bwt = ((t & 1) ? wx : 1.f - wx) * ((t >> 1) ? wy : 1.f - wy);
        twt[k] = valid ? aw * bwt : 0.f;
        tidx[k] = (base + min(max(yi, 0), Wl - 1) * Wl + min(max(xi, 0), Wl - 1)) * 64;
        tsum += twt[k];
    }

    // wsum for bias — full warp reduction
    float ts = tsum;
#pragma unroll
    for (int m = 16; m > 0; m >>= 1)
        ts += __shfl_xor_sync(0xffffffffu, ts, m);

    // ---- dedup within 8-lane level group (16 taps) via shuffles ----
    const int gb = lane & ~7;
    const int pa = (lane & 7) * 2, pb = pa + 1;
    float sumA = 0.f, sumB = 0.f;
    bool fA = true, fB = true;
#pragma unroll
    for (int j = 0; j < 8; ++j) {
        const int src = gb + j;
        const int   ia = __shfl_sync(0xffffffffu, tidx[0], src);
        const int   ib = __shfl_sync(0xffffffffu, tidx[1], src);
        const float wa = __shfl_sync(0xffffffffu, twt[0], src);
        const float wb = __shfl_sync(0xffffffffu, twt[1], src);
        const int qa = 2 * j, qb = 2 * j + 1;
        if (ia == tidx[0]) { sumA += wa; if (qa < pa) fA = false; }
        if (ib == tidx[0]) { sumA += wb; if (qb < pa) fA = false; }
        if (ia == tidx[1]) { sumB += wa; if (qa < pb) fB = false; }
        if (ib == tidx[1]) { sumB += wb; if (qb < pb) fB = false; }
    }
    const float wA = fA ? sumA : 0.f;
    const float wB = fB ? sumB : 0.f;

    // ---- warp-ballot compaction into sC[h]; pad to multiple of 16 ----
    {
        const unsigned mA = __ballot_sync(0xffffffffu, wA != 0.f);
        const int cntA = __popc(mA);
        if (wA != 0.f)
            sC[h][__popc(mA & ((1u << lane) - 1u))] =
                make_float2(wA, __int_as_float(tidx[0]));
        const unsigned mB = __ballot_sync(0xffffffffu, wB != 0.f);
        if (wB != 0.f)
            sC[h][cntA + __popc(mB & ((1u << lane) - 1u))] =
                make_float2(wB, __int_as_float(tidx[1]));
        const int cnt = cntA + __popc(mB);
        const int cntPad = (cnt + 15) & ~15;
        if (lane < cntPad - cnt)
            sC[h][cnt + lane] = make_float2(0.f, __int_as_float(0));
        if (lane == 0) {
            sCnt[h] = cntPad;
            g_wsum[bq * NH + h] = ts;
        }
    }
    __syncthreads();

    // ---- gather: 16-tap batches -> 16 LDG.128 in flight (R5-level MLP) ----
    const int s = tid >> 6;           // slice -> heads 2s, 2s+1
    const int cq = tid & 63;          // channel quad
    const float4* vb = (const float4*)value + (size_t)b * ((size_t)LEN_V * 64) + cq;

#pragma unroll
    for (int hh = 0; hh < 2; ++hh) {
        const int hq = s * 2 + hh;
        const int cntPad = sCnt[hq];  // multiple of 16, uniform per warp
        float accx = 0.f, accy = 0.f, accz = 0.f, accw = 0.f;
        for (int j = 0; j < cntPad; j += 16) {
#pragma unroll
            for (int u = 0; u < 4; ++u) {
                float4 p0 = *(const float4*)&sC[hq][j + u * 4];
                float4 p1 = *(const float4*)&sC[hq][j + u * 4 + 2];
                float4 v0 = vb[__float_as_int(p0.y)];
                float4 v1 = vb[__float_as_int(p0.w)];
                float4 v2 = vb[__float_as_int(p1.y)];
                float4 v3 = vb[__float_as_int(p1.w)];
                accx += p0.x * v0.x + p0.z * v1.x + p1.x * v2.x + p1.z * v3.x;
                accy += p0.x * v0.y + p0.z * v1.y + p1.x * v2.y + p1.z * v3.y;
                accz += p0.x * v0.z + p0.z * v1.z + p1.x * v2.z + p1.z * v3.z;
                accw += p0.x * v0.w + p0.z * v1.w + p1.x * v2.w + p1.z * v3.w;
            }
        }
        *(float4*)&g_agg[(((size_t)hq * NQ) + bq) * DIM + cq * 4] =
            make_float4(accx, accy, accz, accw);
    }
}

// ---------------------------------------------------------------------------
// R5 per-head projection (frozen): tile 32(M) x 64(N), 128 threads, grid (75,4).
// ---------------------------------------------------------------------------
__global__ void headproj_kernel(const float* __restrict__ Wv,
                                const float* __restrict__ bv)
{
    __shared__ float As[2][16][2][36];   // [buf][k][head][row]
    __shared__ float Bs[2][16][68];
    const int tid = threadIdx.x;
    const int tx = tid & 7;
    const int ty = tid >> 3;             // 0..15 ; head = ty>>3
    const int hp = blockIdx.y;
    const int row0 = blockIdx.x * 32;
    const int ar = tid >> 2;             // 0..31
    const int akq = (tid & 3) * 4;
    const int br = tid >> 1;             // 0..63
    const int bkq = (tid & 1) * 8;

    int arow = row0 + ar; if (arow >= NQ) arow = NQ - 1;
    const float* aptr0 = g_agg + (size_t)(2 * hp) * NQ * DIM + (size_t)arow * DIM + akq;
    const float* aptr1 = g_agg + (size_t)(2 * hp + 1) * NQ * DIM + (size_t)arow * DIM + akq;
    const float* wptr  = Wv + (size_t)(hp * 64 + br) * 256 + bkq;

    float acc[4][4];
#pragma unroll
    for (int i = 0; i < 4; ++i)
#pragma unroll
        for (int j = 0; j < 4; ++j) acc[i][j] = 0.f;

    float4 va0 = *(const float4*)(aptr0);
    float4 va1 = *(const float4*)(aptr1);
    float4 vw0 = *(const float4*)(wptr);
    float4 vw1 = *(const float4*)(wptr + 4);

    int buf = 0;
    for (int kc = 0; kc < 256; kc += 16) {
        As[buf][akq + 0][0][ar] = va0.x; As[buf][akq + 1][0][ar] = va0.y;
        As[buf][akq + 2][0][ar] = va0.z; As[buf][akq + 3][0][ar] = va0.w;
        As[buf][akq + 0][1][ar] = va1.x; As[buf][akq + 1][1][ar] = va1.y;
        As[buf][akq + 2][1][ar] = va1.z; As[buf][akq + 3][1][ar] = va1.w;
        Bs[buf][bkq + 0][br] = vw0.x; Bs[buf][bkq + 1][br] = vw0.y;
        Bs[buf][bkq + 2][br] = vw0.z; Bs[buf][bkq + 3][br] = vw0.w;
        Bs[buf][bkq + 4][br] = vw1.x; Bs[buf][bkq + 5][br] = vw1.y;
        Bs[buf][bkq + 6][br] = vw1.z; Bs[buf][bkq + 7][br] = vw1.w;
        __syncthreads();
        if (kc + 16 < 256) {
            va0 = *(const float4*)(aptr0 + kc + 16);
            va1 = *(const float4*)(aptr1 + kc + 16);
            vw0 = *(const float4*)(wptr  + kc + 16);
            vw1 = *(const float4*)(wptr  + kc + 20);
        }
        const int hd = ty >> 3;
#pragma unroll
        for (int k = 0; k < 16; ++k) {
            float4 a4 = ((const float4*)As[buf][k][hd])[tx];
            float4 b4 = ((const float4*)Bs[buf][k])[ty];
            float a[4] = {a4.x, a4.y, a4.z, a4.w};
            float bb[4] = {b4.x, b4.y, b4.z, b4.w};
#pragma unroll
            for (int i = 0; i < 4; ++i)
#pragma unroll
                for (int j = 0; j < 4; ++j)
                    acc[i][j] += a[i] * bb[j];
        }
        buf ^= 1;
    }

    const int gc = hp * 64 + ty * 4;
    const int h = gc >> 5;
    float4 bv4 = make_float4(bv[gc], bv[gc + 1], bv[gc + 2], bv[gc + 3]);
#pragma unroll
    for (int i = 0; i < 4; ++i) {
        int r = row0 + tx * 4 + i;
        if (r < NQ) {
            float ws = g_wsum[r * NH + h];
            float4 o = make_float4(acc[i][0] + ws * bv4.x, acc[i][1] + ws * bv4.y,
                                   acc[i][2] + ws * bv4.z, acc[i][3] + ws * bv4.w);
            *(float4*)(&g_Y[(size_t)r * 256 + gc]) = o;
        }
    }
}

// ---------------------------------------------------------------------------
extern "C" void kernel_launch(void* const* d_in, const int* in_sizes, int n_in,
                              void* d_out, int out_size) {
    const float* query  = (const float*)d_in[0];
    const float* refpts = (const float*)d_in[1];
    const float* value  = (const float*)d_in[2];
    const float* Wv     = (const float*)d_in[3];
    const float* bv     = (const float*)d_in[4];
    const float* Woff   = (const float*)d_in[5];
    const float* boff   = (const float*)d_in[6];
    const float* Wattn  = (const float*)d_in[7];
    const float* battn  = (const float*)d_in[8];
    const float* Wout   = (const float*)d_in[9];
    const float* bout   = (const float*)d_in[10];
    float* out = (float*)d_out;

    float *pP = nullptr, *pY = nullptr;
    cudaGetSymbolAddress((void**)&pP, g_P);
    cudaGetSymbolAddress((void**)&pY, g_Y);

    const int MB = NQ / 32;   // 75

    // qproj: y 0..3 -> Woff (cols 0..255), y 4..5 -> Wattn (cols 256..383)
    gemm_dual_kernel<<<dim3(MB, 6), 128>>>(query, 256, Woff, boff, 4,
                                           Wattn, battn, pP, 384, NQ);
    // fused softmax/loc prep + warp-local dedup + high-MLP gather
    gather_kernel<<<NQ, 256>>>(value, refpts);
    // per-head value projection on aggregates -> g_Y [2400 x 256]
    headproj_kernel<<<dim3(MB, 4), 128>>>(Wv, bv);
    // output projection -> out
    gemm_dual_kernel<<<dim3(MB, 4), 128>>>(pY, 256, Wout, bout, 4,
                                           (const float*)nullptr,
                                           (const float*)nullptr, out, 256, NQ);
}

// round 16
// speedup vs baseline: 1.0173x; 1.0173x over previous
#include <cuda_runtime.h>
#include <math.h>

#define BS 8
#define LQ 300
#define NQ (BS*LQ)        // 2400
#define DIM 256
#define NH 8
#define NL 4
#define NP 4
#define LEN_V 34000
#define NPOINT 128        // NH*NL*NP

__constant__ int c_lvlW[4]     = {160, 80, 40, 20};
__constant__ int c_lvlStart[4] = {0, 25600, 32000, 33600};

// Scratch
__device__ float g_P[NQ * 384];                    // [off(256) | attn(128)]
__device__ float g_agg[(size_t)NH * NQ * DIM];     // [h][q][c]
__device__ float g_wsum[NQ * NH];
__device__ float g_Y[NQ * DIM];

// ---------------------------------------------------------------------------
// R5 GEMM (frozen): tile 32(M) x 64(N), 128 threads, micro 4x4, double-buffer.
// ---------------------------------------------------------------------------
__global__ void gemm_dual_kernel(const float* __restrict__ A, int lda,
                                 const float* __restrict__ W0,
                                 const float* __restrict__ b0, int nyW0,
                                 const float* __restrict__ W1,
                                 const float* __restrict__ b1,
                                 float* __restrict__ C, int ldc, int M)
{
    __shared__ float As[2][16][36];
    __shared__ float Bs[2][16][68];
    const int tid = threadIdx.x;
    const int tx = tid & 7;           // m-quad
    const int ty = tid >> 3;          // n-quad 0..15
    const int row0 = blockIdx.x * 32;
    const int ar = tid >> 2;          // 0..31 (A load row)
    const int akq = (tid & 3) * 4;
    const int br = tid >> 1;          // 0..63 (B load col)
    const int bkq = (tid & 1) * 8;

    const float* W; const float* bias; int col0, colOff;
    if ((int)blockIdx.y < nyW0) {
        W = W0; bias = b0; col0 = blockIdx.y * 64; colOff = 0;
    } else {
        W = W1; bias = b1; col0 = (blockIdx.y - nyW0) * 64; colOff = nyW0 * 64;
    }

    int arow = row0 + ar; if (arow >= M) arow = M - 1;
    const float* aptr = A + (size_t)arow * lda + akq;
    const float* wptr = W + (size_t)(col0 + br) * 256 + bkq;

    float acc[2][4];
    float acc2[2][4];
#pragma unroll
    for (int i = 0; i < 2; ++i)
#pragma unroll
        for (int j = 0; j < 4; ++j) { acc[i][j] = 0.f; acc2[i][j] = 0.f; }

    float4 va  = *(const float4*)(aptr);
    float4 vw0 = *(const float4*)(wptr);
    float4 vw1 = *(const float4*)(wptr + 4);

    int buf = 0;
    for (int kc = 0; kc < 256; kc += 16) {
        As[buf][akq + 0][ar] = va.x;  As[buf][akq + 1][ar] = va.y;
        As[buf][akq + 2][ar] = va.z;  As[buf][akq + 3][ar] = va.w;
        Bs[buf][bkq + 0][br] = vw0.x; Bs[buf][bkq + 1][br] = vw0.y;
        Bs[buf][bkq + 2][br] = vw0.z; Bs[buf][bkq + 3][br] = vw0.w;
        Bs[buf][bkq + 4][br] = vw1.x; Bs[buf][bkq + 5][br] = vw1.y;
        Bs[buf][bkq + 6][br] = vw1.z; Bs[buf][bkq + 7][br] = vw1.w;
        __syncthreads();
        if (kc + 16 < 256) {
            va  = *(const float4*)(aptr + kc + 16);
            vw0 = *(const float4*)(wptr + kc + 16);
            vw1 = *(const float4*)(wptr + kc + 20);
        }
#pragma unroll
        for (int k = 0; k < 16; ++k) {
            float4 a4 = ((const float4*)As[buf][k])[tx];
            float4 b4 = ((const float4*)Bs[buf][k])[ty];
            acc[0][0] += a4.x * b4.x; acc[0][1] += a4.x * b4.y;
            acc[0][2] += a4.x * b4.z; acc[0][3] += a4.x * b4.w;
            acc[1][0] += a4.y * b4.x; acc[1][1] += a4.y * b4.y;
            acc[1][2] += a4.y * b4.z; acc[1][3] += a4.y * b4.w;
            acc2[0][0] += a4.z * b4.x; acc2[0][1] += a4.z * b4.y;
            acc2[0][2] += a4.z * b4.z; acc2[0][3] += a4.z * b4.w;
            acc2[1][0] += a4.w * b4.x; acc2[1][1] += a4.w * b4.y;
            acc2[1][2] += a4.w * b4.z; acc2[1][3] += a4.w * b4.w;
        }
        buf ^= 1;
    }

    const int gc = col0 + ty * 4;
    float4 bv4 = make_float4(bias[gc], bias[gc + 1], bias[gc + 2], bias[gc + 3]);
#pragma unroll
    for (int i = 0; i < 4; ++i) {
        int r = row0 + tx * 4 + i;
        if (r < M) {
            float* a = (i < 2) ? acc[i] : acc2[i - 2];
            float4 o = make_float4(a[0] + bv4.x, a[1] + bv4.y,
                                   a[2] + bv4.z, a[3] + bv4.w);
            *(float4*)(&C[(size_t)r * ldc + colOff + gc]) = o;
        }
    }
}

// ---------------------------------------------------------------------------
// Fused prep + gather: exact R5 prep; main loop processes BOTH heads of the
// slice interleaved (two independent load streams, no inter-head drain).
// ---------------------------------------------------------------------------
__global__ void __launch_bounds__(256) gather_kernel(
    const float* __restrict__ value, const float* __restrict__ refpts)
{
    __shared__ float4 sPt4[NH * 32];
    __shared__ float  sm_aw[NPOINT];
    __shared__ float  sWsum[NH];

    const int bq = blockIdx.x;
    const int b = bq / LQ;
    const int tid = threadIdx.x;

    if (tid < NH) sWsum[tid] = 0.f;
    if (tid < NPOINT) sm_aw[tid] = g_P[bq * 384 + 256 + tid];
    __syncthreads();

    if (tid < NPOINT) {
        const int p = tid;
        const int h = p >> 4;
        const int rem = p & 15;
        const int l = rem >> 2;
        const int pt = rem & 3;

        float a = sm_aw[p];
        float mx = -1e30f;
#pragma unroll
        for (int i = 0; i < 16; ++i) mx = fmaxf(mx, sm_aw[h * 16 + i]);
        float ssum = 0.f;
#pragma unroll
        for (int i = 0; i < 16; ++i) ssum += expf(sm_aw[h * 16 + i] - mx);
        float w = expf(a - mx) / ssum;

        const int Wl = c_lvlW[l];
        const int base = c_lvlStart[l];
        const float fW = (float)Wl;
        float offx = g_P[bq * 384 + (((h * 4 + l) * 4 + pt) * 2) + 0];
        float offy = g_P[bq * 384 + (((h * 4 + l) * 4 + pt) * 2) + 1];
        float rx = refpts[(bq * NL + l) * 2 + 0];
        float ry = refpts[(bq * NL + l) * 2 + 1];
        float x = (rx + offx / fW) * fW - 0.5f;
        float y = (ry + offy / fW) * fW - 0.5f;

        const float fx = floorf(x), fy = floorf(y);
        const int x0 = (int)fx, y0 = (int)fy;
        const float wx = x - fx, wy = y - fy;
        const float bw[4] = {(1.f - wx) * (1.f - wy), wx * (1.f - wy),
                             (1.f - wx) * wy,         wx * wy};
        const int dx[4] = {0, 1, 0, 1};
        const int dy[4] = {0, 0, 1, 1};
        float wt[4]; int idx4[4];
        float tsum = 0.f;
#pragma unroll
        for (int t = 0; t < 4; ++t) {
            int xi = x0 + dx[t], yi = y0 + dy[t];
            bool valid = (xi >= 0) && (xi < Wl) && (yi >= 0) && (yi < Wl);
            wt[t] = valid ? w * bw[t] : 0.f;
            int xc = min(max(xi, 0), Wl - 1);
            int yc = min(max(yi, 0), Wl - 1);
            idx4[t] = (base + yc * Wl + xc) * 64;
            tsum += wt[t];
        }
        sPt4[h * 32 + rem * 2 + 0] =
            make_float4(wt[0], __int_as_float(idx4[0]), wt[1], __int_as_float(idx4[1]));
        sPt4[h * 32 + rem * 2 + 1] =
            make_float4(wt[2], __int_as_float(idx4[2]), wt[3], __int_as_float(idx4[3]));
        atomicAdd(&sWsum[h], tsum);
    }
    __syncthreads();

    const int s = tid >> 6;           // slice -> heads 2s, 2s+1
    const int cq = tid & 63;          // channel quad
    const float4* vb = (const float4*)value + (size_t)b * ((size_t)LEN_V * 64) + cq;
    const int h0 = s * 2, h1 = s * 2 + 1;

    float a0x = 0.f, a0y = 0.f, a0z = 0.f, a0w = 0.f;
    float a1x = 0.f, a1y = 0.f, a1z = 0.f, a1w = 0.f;
#pragma unroll 2
    for (int j = 0; j < 32; j += 2) {
        float4 p0 = sPt4[h0 * 32 + j];
        float4 p1 = sPt4[h0 * 32 + j + 1];
        float4 q0 = sPt4[h1 * 32 + j];
        float4 q1 = sPt4[h1 * 32 + j + 1];
        float4 v0 = vb[__float_as_int(p0.y)];
        float4 v1 = vb[__float_as_int(p0.w)];
        float4 v2 = vb[__float_as_int(p1.y)];
        float4 v3 = vb[__float_as_int(p1.w)];
        float4 u0 = vb[__float_as_int(q0.y)];
        float4 u1 = vb[__float_as_int(q0.w)];
        float4 u2 = vb[__float_as_int(q1.y)];
        float4 u3 = vb[__float_as_int(q1.w)];
        a0x += p0.x * v0.x + p0.z * v1.x + p1.x * v2.x + p1.z * v3.x;
        a0y += p0.x * v0.y + p0.z * v1.y + p1.x * v2.y + p1.z * v3.y;
        a0z += p0.x * v0.z + p0.z * v1.z + p1.x * v2.z + p1.z * v3.z;
        a0w += p0.x * v0.w + p0.z * v1.w + p1.x * v2.w + p1.z * v3.w;
        a1x += q0.x * u0.x + q0.z * u1.x + q1.x * u2.x + q1.z * u3.x;
        a1y += q0.x * u0.y + q0.z * u1.y + q1.x * u2.y + q1.z * u3.y;
        a1z += q0.x * u0.z + q0.z * u1.z + q1.x * u2.z + q1.z * u3.z;
        a1w += q0.x * u0.w + q0.z * u1.w + q1.x * u2.w + q1.z * u3.w;
    }
    *(float4*)&g_agg[(((size_t)h0 * NQ) + bq) * DIM + cq * 4] =
        make_float4(a0x, a0y, a0z, a0w);
    *(float4*)&g_agg[(((size_t)h1 * NQ) + bq) * DIM + cq * 4] =
        make_float4(a1x, a1y, a1z, a1w);
    if (tid < NH) g_wsum[bq * NH + tid] = sWsum[tid];
}

// ---------------------------------------------------------------------------
// R5 per-head projection (frozen): tile 32(M) x 64(N), 128 threads, grid (75,4).
// ---------------------------------------------------------------------------
__global__ void headproj_kernel(const float* __restrict__ Wv,
                                const float* __restrict__ bv)
{
    __shared__ float As[2][16][2][36];   // [buf][k][head][row]
    __shared__ float Bs[2][16][68];
    const int tid = threadIdx.x;
    const int tx = tid & 7;
    const int ty = tid >> 3;             // 0..15 ; head = ty>>3
    const int hp = blockIdx.y;
    const int row0 = blockIdx.x * 32;
    const int ar = tid >> 2;             // 0..31
    const int akq = (tid & 3) * 4;
    const int br = tid >> 1;             // 0..63
    const int bkq = (tid & 1) * 8;

    int arow = row0 + ar; if (arow >= NQ) arow = NQ - 1;
    const float* aptr0 = g_agg + (size_t)(2 * hp) * NQ * DIM + (size_t)arow * DIM + akq;
    const float* aptr1 = g_agg + (size_t)(2 * hp + 1) * NQ * DIM + (size_t)arow * DIM + akq;
    const float* wptr  = Wv + (size_t)(hp * 64 + br) * 256 + bkq;

    float acc[4][4];
#pragma unroll
    for (int i = 0; i < 4; ++i)
#pragma unroll
        for (int j = 0; j < 4; ++j) acc[i][j] = 0.f;

    float4 va0 = *(const float4*)(aptr0);
    float4 va1 = *(const float4*)(aptr1);
    float4 vw0 = *(const float4*)(wptr);
    float4 vw1 = *(const float4*)(wptr + 4);

    int buf = 0;
    for (int kc = 0; kc < 256; kc += 16) {
        As[buf][akq + 0][0][ar] = va0.x; As[buf][akq + 1][0][ar] = va0.y;
        As[buf][akq + 2][0][ar] = va0.z; As[buf][akq + 3][0][ar] = va0.w;
        As[buf][akq + 0][1][ar] = va1.x; As[buf][akq + 1][1][ar] = va1.y;
        As[buf][akq + 2][1][ar] = va1.z; As[buf][akq + 3][1][ar] = va1.w;
        Bs[buf][bkq + 0][br] = vw0.x; Bs[buf][bkq + 1][br] = vw0.y;
        Bs[buf][bkq + 2][br] = vw0.z; Bs[buf][bkq + 3][br] = vw0.w;
        Bs[buf][bkq + 4][br] = vw1.x; Bs[buf][bkq + 5][br] = vw1.y;
        Bs[buf][bkq + 6][br] = vw1.z; Bs[buf][bkq + 7][br] = vw1.w;
        __syncthreads();
        if (kc + 16 < 256) {
            va0 = *(const float4*)(aptr0 + kc + 16);
            va1 = *(const float4*)(aptr1 + kc + 16);
            vw0 = *(const float4*)(wptr  + kc + 16);
            vw1 = *(const float4*)(wptr  + kc + 20);
        }
        const int hd = ty >> 3;
#pragma unroll
        for (int k = 0; k < 16; ++k) {
            float4 a4 = ((const float4*)As[buf][k][hd])[tx];
            float4 b4 = ((const float4*)Bs[buf][k])[ty];
            float a[4] = {a4.x, a4.y, a4.z, a4.w};
            float bb[4] = {b4.x, b4.y, b4.z, b4.w};
#pragma unroll
            for (int i = 0; i < 4; ++i)
#pragma unroll
                for (int j = 0; j < 4; ++j)
                    acc[i][j] += a[i] * bb[j];
        }
        buf ^= 1;
    }

    const int gc = hp * 64 + ty * 4;
    const int h = gc >> 5;
    float4 bv4 = make_float4(bv[gc], bv[gc + 1], bv[gc + 2], bv[gc + 3]);
#pragma unroll
    for (int i = 0; i < 4; ++i) {
        int r = row0 + tx * 4 + i;
        if (r < NQ) {
            float ws = g_wsum[r * NH + h];
            float4 o = make_float4(acc[i][0] + ws * bv4.x, acc[i][1] + ws * bv4.y,
                                   acc[i][2] + ws * bv4.z, acc[i][3] + ws * bv4.w);
            *(float4*)(&g_Y[(size_t)r * 256 + gc]) = o;
        }
    }
}

// ---------------------------------------------------------------------------
extern "C" void kernel_launch(void* const* d_in, const int* in_sizes, int n_in,
                              void* d_out, int out_size) {
    const float* query  = (const float*)d_in[0];
    const float* refpts = (const float*)d_in[1];
    const float* value  = (const float*)d_in[2];
    const float* Wv     = (const float*)d_in[3];
    const float* bv     = (const float*)d_in[4];
    const float* Woff   = (const float*)d_in[5];
    const float* boff   = (const float*)d_in[6];
    const float* Wattn  = (const float*)d_in[7];
    const float* battn  = (const float*)d_in[8];
    const float* Wout   = (const float*)d_in[9];
    const float* bout   = (const float*)d_in[10];
    float* out = (float*)d_out;

    float *pP = nullptr, *pY = nullptr;
    cudaGetSymbolAddress((void**)&pP, g_P);
    cudaGetSymbolAddress((void**)&pY, g_Y);

    const int MB = NQ / 32;   // 75

    // qproj: y 0..3 -> Woff (cols 0..255), y 4..5 -> Wattn (cols 256..383)
    gemm_dual_kernel<<<dim3(MB, 6), 128>>>(query, 256, Woff, boff, 4,
                                           Wattn, battn, pP, 384, NQ);
    // fused softmax/loc prep + dual-head interleaved gather
    gather_kernel<<<NQ, 256>>>(value, refpts);
    // per-head value projection on aggregates -> g_Y [2400 x 256]
    headproj_kernel<<<dim3(MB, 4), 128>>>(Wv, bv);
    // output projection -> out
    gemm_dual_kernel<<<dim3(MB, 4), 128>>>(pY, 256, Wout, bout, 4,
                                           (const float*)nullptr,
                                           (const float*)nullptr, out, 256, NQ);
}

// round 17
// speedup vs baseline: 1.0354x; 1.0178x over previous
#include <cuda_runtime.h>
#include <math.h>

#define BS 8
#define LQ 300
#define NQ (BS*LQ)        // 2400
#define DIM 256
#define NH 8
#define NL 4
#define NP 4
#define LEN_V 34000
#define NPOINT 128        // NH*NL*NP

__constant__ int c_lvlW[4]     = {160, 80, 40, 20};
__constant__ int c_lvlStart[4] = {0, 25600, 32000, 33600};

// Scratch
__device__ float g_P[NQ * 384];                    // [off(256) | attn(128)]
__device__ float g_agg[(size_t)NH * NQ * DIM];     // [h][q][c]
__device__ float g_wsum[NQ * NH];
__device__ float g_Y[NQ * DIM];

// ---------------------------------------------------------------------------
// R5 GEMM (frozen): tile 32(M) x 64(N), 128 threads, micro 4x4, double-buffer.
// ---------------------------------------------------------------------------
__global__ void gemm_dual_kernel(const float* __restrict__ A, int lda,
                                 const float* __restrict__ W0,
                                 const float* __restrict__ b0, int nyW0,
                                 const float* __restrict__ W1,
                                 const float* __restrict__ b1,
                                 float* __restrict__ C, int ldc, int M)
{
    __shared__ float As[2][16][36];
    __shared__ float Bs[2][16][68];
    const int tid = threadIdx.x;
    const int tx = tid & 7;           // m-quad
    const int ty = tid >> 3;          // n-quad 0..15
    const int row0 = blockIdx.x * 32;
    const int ar = tid >> 2;          // 0..31 (A load row)
    const int akq = (tid & 3) * 4;
    const int br = tid >> 1;          // 0..63 (B load col)
    const int bkq = (tid & 1) * 8;

    const float* W; const float* bias; int col0, colOff;
    if ((int)blockIdx.y < nyW0) {
        W = W0; bias = b0; col0 = blockIdx.y * 64; colOff = 0;
    } else {
        W = W1; bias = b1; col0 = (blockIdx.y - nyW0) * 64; colOff = nyW0 * 64;
    }

    int arow = row0 + ar; if (arow >= M) arow = M - 1;
    const float* aptr = A + (size_t)arow * lda + akq;
    const float* wptr = W + (size_t)(col0 + br) * 256 + bkq;

    float acc[2][4];
    float acc2[2][4];
#pragma unroll
    for (int i = 0; i < 2; ++i)
#pragma unroll
        for (int j = 0; j < 4; ++j) { acc[i][j] = 0.f; acc2[i][j] = 0.f; }

    float4 va  = *(const float4*)(aptr);
    float4 vw0 = *(const float4*)(wptr);
    float4 vw1 = *(const float4*)(wptr + 4);

    int buf = 0;
    for (int kc = 0; kc < 256; kc += 16) {
        As[buf][akq + 0][ar] = va.x;  As[buf][akq + 1][ar] = va.y;
        As[buf][akq + 2][ar] = va.z;  As[buf][akq + 3][ar] = va.w;
        Bs[buf][bkq + 0][br] = vw0.x; Bs[buf][bkq + 1][br] = vw0.y;
        Bs[buf][bkq + 2][br] = vw0.z; Bs[buf][bkq + 3][br] = vw0.w;
        Bs[buf][bkq + 4][br] = vw1.x; Bs[buf][bkq + 5][br] = vw1.y;
        Bs[buf][bkq + 6][br] = vw1.z; Bs[buf][bkq + 7][br] = vw1.w;
        __syncthreads();
        if (kc + 16 < 256) {
            va  = *(const float4*)(aptr + kc + 16);
            vw0 = *(const float4*)(wptr + kc + 16);
            vw1 = *(const float4*)(wptr + kc + 20);
        }
#pragma unroll
        for (int k = 0; k < 16; ++k) {
            float4 a4 = ((const float4*)As[buf][k])[tx];
            float4 b4 = ((const float4*)Bs[buf][k])[ty];
            acc[0][0] += a4.x * b4.x; acc[0][1] += a4.x * b4.y;
            acc[0][2] += a4.x * b4.z; acc[0][3] += a4.x * b4.w;
            acc[1][0] += a4.y * b4.x; acc[1][1] += a4.y * b4.y;
            acc[1][2] += a4.y * b4.z; acc[1][3] += a4.y * b4.w;
            acc2[0][0] += a4.z * b4.x; acc2[0][1] += a4.z * b4.y;
            acc2[0][2] += a4.z * b4.z; acc2[0][3] += a4.z * b4.w;
            acc2[1][0] += a4.w * b4.x; acc2[1][1] += a4.w * b4.y;
            acc2[1][2] += a4.w * b4.z; acc2[1][3] += a4.w * b4.w;
        }
        buf ^= 1;
    }

    const int gc = col0 + ty * 4;
    float4 bv4 = make_float4(bias[gc], bias[gc + 1], bias[gc + 2], bias[gc + 3]);
#pragma unroll
    for (int i = 0; i < 4; ++i) {
        int r = row0 + tx * 4 + i;
        if (r < M) {
            float* a = (i < 2) ? acc[i] : acc2[i - 2];
            float4 o = make_float4(a[0] + bv4.x, a[1] + bv4.y,
                                   a[2] + bv4.z, a[3] + bv4.w);
            *(float4*)(&C[(size_t)r * ldc + colOff + gc]) = o;
        }
    }
}

// ---------------------------------------------------------------------------
// Fused prep + gather: exact R5 structure; wsum via width-16 shuffle
// reduction instead of smem atomics (strictly cheaper prologue).
// ---------------------------------------------------------------------------
__global__ void __launch_bounds__(256) gather_kernel(
    const float* __restrict__ value, const float* __restrict__ refpts)
{
    __shared__ float4 sPt4[NH * 32];
    __shared__ float  sm_aw[NPOINT];

    const int bq = blockIdx.x;
    const int b = bq / LQ;
    const int tid = threadIdx.x;

    if (tid < NPOINT) sm_aw[tid] = g_P[bq * 384 + 256 + tid];
    __syncthreads();

    if (tid < NPOINT) {
        const int p = tid;
        const int h = p >> 4;
        const int rem = p & 15;
        const int l = rem >> 2;
        const int pt = rem & 3;

        float a = sm_aw[p];
        float mx = -1e30f;
#pragma unroll
        for (int i = 0; i < 16; ++i) mx = fmaxf(mx, sm_aw[h * 16 + i]);
        float ssum = 0.f;
#pragma unroll
        for (int i = 0; i < 16; ++i) ssum += expf(sm_aw[h * 16 + i] - mx);
        float w = expf(a - mx) / ssum;

        const int Wl = c_lvlW[l];
        const int base = c_lvlStart[l];
        const float fW = (float)Wl;
        float offx = g_P[bq * 384 + (((h * 4 + l) * 4 + pt) * 2) + 0];
        float offy = g_P[bq * 384 + (((h * 4 + l) * 4 + pt) * 2) + 1];
        float rx = refpts[(bq * NL + l) * 2 + 0];
        float ry = refpts[(bq * NL + l) * 2 + 1];
        float x = (rx + offx / fW) * fW - 0.5f;
        float y = (ry + offy / fW) * fW - 0.5f;

        const float fx = floorf(x), fy = floorf(y);
        const int x0 = (int)fx, y0 = (int)fy;
        const float wx = x - fx, wy = y - fy;
        const float bw[4] = {(1.f - wx) * (1.f - wy), wx * (1.f - wy),
                             (1.f - wx) * wy,         wx * wy};
        const int dx[4] = {0, 1, 0, 1};
        const int dy[4] = {0, 0, 1, 1};
        float wt[4]; int idx4[4];
        float tsum = 0.f;
#pragma unroll
        for (int t = 0; t < 4; ++t) {
            int xi = x0 + dx[t], yi = y0 + dy[t];
            bool valid = (xi >= 0) && (xi < Wl) && (yi >= 0) && (yi < Wl);
            wt[t] = valid ? w * bw[t] : 0.f;
            int xc = min(max(xi, 0), Wl - 1);
            int yc = min(max(yi, 0), Wl - 1);
            idx4[t] = (base + yc * Wl + xc) * 64;
            tsum += wt[t];
        }
        sPt4[h * 32 + rem * 2 + 0] =
            make_float4(wt[0], __int_as_float(idx4[0]), wt[1], __int_as_float(idx4[1]));
        sPt4[h * 32 + rem * 2 + 1] =
            make_float4(wt[2], __int_as_float(idx4[2]), wt[3], __int_as_float(idx4[3]));

        // wsum for head h = sum of tsum over its 16 threads (width-16 shuffle)
#pragma unroll
        for (int m = 8; m > 0; m >>= 1)
            tsum += __shfl_xor_sync(0xffffffffu, tsum, m, 16);
        if (rem == 0) g_wsum[bq * NH + h] = tsum;
    }
    __syncthreads();

    const int s = tid >> 6;           // slice 0..3 -> heads 2s, 2s+1
    const int cq = tid & 63;          // channel quad
    const float4* vb = (const float4*)value + (size_t)b * ((size_t)LEN_V * 64) + cq;

#pragma unroll
    for (int hh = 0; hh < 2; ++hh) {
        const int h = s * 2 + hh;
        float accx = 0.f, accy = 0.f, accz = 0.f, accw = 0.f;
#pragma unroll 4
        for (int j = 0; j < 32; j += 2) {
            float4 p0 = sPt4[h * 32 + j];
            float4 p1 = sPt4[h * 32 + j + 1];
            float4 v0 = vb[__float_as_int(p0.y)];
            float4 v1 = vb[__float_as_int(p0.w)];
            float4 v2 = vb[__float_as_int(p1.y)];
            float4 v3 = vb[__float_as_int(p1.w)];
            accx += p0.x * v0.x + p0.z * v1.x + p1.x * v2.x + p1.z * v3.x;
            accy += p0.x * v0.y + p0.z * v1.y + p1.x * v2.y + p1.z * v3.y;
            accz += p0.x * v0.z + p0.z * v1.z + p1.x * v2.z + p1.z * v3.z;
            accw += p0.x * v0.w + p0.z * v1.w + p1.x * v2.w + p1.z * v3.w;
        }
        *(float4*)&g_agg[(((size_t)h * NQ) + bq) * DIM + cq * 4] =
            make_float4(accx, accy, accz, accw);
    }
}

// ---------------------------------------------------------------------------
// R5 per-head projection (frozen): tile 32(M) x 64(N), 128 threads, grid (75,4).
// ---------------------------------------------------------------------------
__global__ void headproj_kernel(const float* __restrict__ Wv,
                                const float* __restrict__ bv)
{
    __shared__ float As[2][16][2][36];   // [buf][k][head][row]
    __shared__ float Bs[2][16][68];
    const int tid = threadIdx.x;
    const int tx = tid & 7;
    const int ty = tid >> 3;             // 0..15 ; head = ty>>3
    const int hp = blockIdx.y;
    const int row0 = blockIdx.x * 32;
    const int ar = tid >> 2;             // 0..31
    const int akq = (tid & 3) * 4;
    const int br = tid >> 1;             // 0..63
    const int bkq = (tid & 1) * 8;

    int arow = row0 + ar; if (arow >= NQ) arow = NQ - 1;
    const float* aptr0 = g_agg + (size_t)(2 * hp) * NQ * DIM + (size_t)arow * DIM + akq;
    const float* aptr1 = g_agg + (size_t)(2 * hp + 1) * NQ * DIM + (size_t)arow * DIM + akq;
    const float* wptr  = Wv + (size_t)(hp * 64 + br) * 256 + bkq;

    float acc[4][4];
#pragma unroll
    for (int i = 0; i < 4; ++i)
#pragma unroll
        for (int j = 0; j < 4; ++j) acc[i][j] = 0.f;

    float4 va0 = *(const float4*)(aptr0);
    float4 va1 = *(const float4*)(aptr1);
    float4 vw0 = *(const float4*)(wptr);
    float4 vw1 = *(const float4*)(wptr + 4);

    int buf = 0;
    for (int kc = 0; kc < 256; kc += 16) {
        As[buf][akq + 0][0][ar] = va0.x; As[buf][akq + 1][0][ar] = va0.y;
        As[buf][akq + 2][0][ar] = va0.z; As[buf][akq + 3][0][ar] = va0.w;
        As[buf][akq + 0][1][ar] = va1.x; As[buf][akq + 1][1][ar] = va1.y;
        As[buf][akq + 2][1][ar] = va1.z; As[buf][akq + 3][1][ar] = va1.w;
        Bs[buf][bkq + 0][br] = vw0.x; Bs[buf][bkq + 1][br] = vw0.y;
        Bs[buf][bkq + 2][br] = vw0.z; Bs[buf][bkq + 3][br] = vw0.w;
        Bs[buf][bkq + 4][br] = vw1.x; Bs[buf][bkq + 5][br] = vw1.y;
        Bs[buf][bkq + 6][br] = vw1.z; Bs[buf][bkq + 7][br] = vw1.w;
        __syncthreads();
        if (kc + 16 < 256) {
            va0 = *(const float4*)(aptr0 + kc + 16);
            va1 = *(const float4*)(aptr1 + kc + 16);
            vw0 = *(const float4*)(wptr  + kc + 16);
            vw1 = *(const float4*)(wptr  + kc + 20);
        }
        const int hd = ty >> 3;
#pragma unroll
        for (int k = 0; k < 16; ++k) {
            float4 a4 = ((const float4*)As[buf][k][hd])[tx];
            float4 b4 = ((const float4*)Bs[buf][k])[ty];
            float a[4] = {a4.x, a4.y, a4.z, a4.w};
            float bb[4] = {b4.x, b4.y, b4.z, b4.w};
#pragma unroll
            for (int i = 0; i < 4; ++i)
#pragma unroll
                for (int j = 0; j < 4; ++j)
                    acc[i][j] += a[i] * bb[j];
        }
        buf ^= 1;
    }

    const int gc = hp * 64 + ty * 4;
    const int h = gc >> 5;
    float4 bv4 = make_float4(bv[gc], bv[gc + 1], bv[gc + 2], bv[gc + 3]);
#pragma unroll
    for (int i = 0; i < 4; ++i) {
        int r = row0 + tx * 4 + i;
        if (r < NQ) {
            float ws = g_wsum[r * NH + h];
            float4 o = make_float4(acc[i][0] + ws * bv4.x, acc[i][1] + ws * bv4.y,
                                   acc[i][2] + ws * bv4.z, acc[i][3] + ws * bv4.w);
            *(float4*)(&g_Y[(size_t)r * 256 + gc]) = o;
        }
    }
}

// ---------------------------------------------------------------------------
extern "C" void kernel_launch(void* const* d_in, const int* in_sizes, int n_in,
                              void* d_out, int out_size) {
    const float* query  = (const float*)d_in[0];
    const float* refpts = (const float*)d_in[1];
    const float* value  = (const float*)d_in[2];
    const float* Wv     = (const float*)d_in[3];
    const float* bv     = (const float*)d_in[4];
    const float* Woff   = (const float*)d_in[5];
    const float* boff   = (const float*)d_in[6];
    const float* Wattn  = (const float*)d_in[7];
    const float* battn  = (const float*)d_in[8];
    const float* Wout   = (const float*)d_in[9];
    const float* bout   = (const float*)d_in[10];
    float* out = (float*)d_out;

    float *pP = nullptr, *pY = nullptr;
    cudaGetSymbolAddress((void**)&pP, g_P);
    cudaGetSymbolAddress((void**)&pY, g_Y);

    const int MB = NQ / 32;   // 75

    // qproj: y 0..3 -> Woff (cols 0..255), y 4..5 -> Wattn (cols 256..383)
    gemm_dual_kernel<<<dim3(MB, 6), 128>>>(query, 256, Woff, boff, 4,
                                           Wattn, battn, pP, 384, NQ);
    // fused softmax/loc prep + weighted value gather
    gather_kernel<<<NQ, 256>>>(value, refpts);
    // per-head value projection on aggregates -> g_Y [2400 x 256]
    headproj_kernel<<<dim3(MB, 4), 128>>>(Wv, bv);
    // output projection -> out
    gemm_dual_kernel<<<dim3(MB, 4), 128>>>(pY, 256, Wout, bout, 4,
                                           (const float*)nullptr,
                                           (const float*)nullptr, out, 256, NQ);
}